// round 2
// baseline (speedup 1.0000x reference)
#include <cuda_runtime.h>

#define NN 100000
#define NE 640000
#define NF 128
#define NC 16

// Scratch (allocation-free rule: __device__ globals)
__device__ float g_yl[NN * NC];   // x @ W_l^T
__device__ float g_yr[NN * NC];   // x @ W_r^T
__device__ float g_agg[NN * NC];  // segment-sum of yl over edges
__device__ float g_deg[NN];       // in-degree (float)

// ---------------------------------------------------------------------------
// K0: zero agg + deg
// ---------------------------------------------------------------------------
__global__ void k_zero() {
    int i = blockIdx.x * blockDim.x + threadIdx.x;
    if (i < NN * 4) reinterpret_cast<float4*>(g_agg)[i] = make_float4(0.f, 0.f, 0.f, 0.f);
    if (i < NN) g_deg[i] = 0.f;
}

// ---------------------------------------------------------------------------
// K1: fused dual projection  yl = x @ W_l^T, yr = x @ W_r^T
// One thread per node. Weights (32 rows x 128) in smem, broadcast reads.
// ---------------------------------------------------------------------------
__global__ __launch_bounds__(256) void k_proj(const float* __restrict__ x,
                                              const float* __restrict__ Wl,
                                              const float* __restrict__ Wr) {
    __shared__ float4 sW[32 * 32];  // [c][k4]: c<16 -> W_l rows, c>=16 -> W_r rows
    int tid = threadIdx.x;
    for (int j = tid; j < 32 * 32; j += 256) {
        int c = j >> 5;
        int k4 = j & 31;
        const float* wrow = (c < 16) ? (Wl + c * NF) : (Wr + (c - 16) * NF);
        sW[j] = reinterpret_cast<const float4*>(wrow)[k4];
    }
    __syncthreads();

    int i = blockIdx.x * 256 + tid;
    if (i >= NN) return;

    float acc[32];
#pragma unroll
    for (int c = 0; c < 32; c++) acc[c] = 0.f;

    const float4* xr = reinterpret_cast<const float4*>(x + (size_t)i * NF);
#pragma unroll 4
    for (int k4 = 0; k4 < 32; k4++) {
        float4 xv = xr[k4];
#pragma unroll
        for (int c = 0; c < 32; c++) {
            float4 wv = sW[c * 32 + k4];
            acc[c] = fmaf(xv.x, wv.x, acc[c]);
            acc[c] = fmaf(xv.y, wv.y, acc[c]);
            acc[c] = fmaf(xv.z, wv.z, acc[c]);
            acc[c] = fmaf(xv.w, wv.w, acc[c]);
        }
    }

    float4* yl4 = reinterpret_cast<float4*>(g_yl + (size_t)i * NC);
    float4* yr4 = reinterpret_cast<float4*>(g_yr + (size_t)i * NC);
#pragma unroll
    for (int q = 0; q < 4; q++) {
        yl4[q] = make_float4(acc[q * 4 + 0], acc[q * 4 + 1], acc[q * 4 + 2], acc[q * 4 + 3]);
        yr4[q] = make_float4(acc[16 + q * 4 + 0], acc[16 + q * 4 + 1],
                             acc[16 + q * 4 + 2], acc[16 + q * 4 + 3]);
    }
}

// ---------------------------------------------------------------------------
// K2: edge scatter. edge_index is INT32 (JAX x64 disabled downcasts int64).
// One thread per edge: gather yl[src] (64B, L2-resident), vectorized f32
// reduction-add into agg[dst], plus one degree atomic.
// ---------------------------------------------------------------------------
__global__ __launch_bounds__(256) void k_scatter(const int* __restrict__ ei) {
    int e = blockIdx.x * blockDim.x + threadIdx.x;
    if (e >= NE) return;
    unsigned src = (unsigned)ei[e];
    unsigned dst = (unsigned)ei[NE + e];
    if (src >= NN || dst >= NN) return;  // never taken with valid input; avoids faults

    const float4* ysrc = reinterpret_cast<const float4*>(g_yl + (size_t)src * NC);
    float* d = g_agg + (size_t)dst * NC;
#pragma unroll
    for (int q = 0; q < 4; q++) {
        float4 v = ysrc[q];
        asm volatile("red.global.add.v4.f32 [%0], {%1, %2, %3, %4};"
                     :: "l"(d + q * 4), "f"(v.x), "f"(v.y), "f"(v.z), "f"(v.w)
                     : "memory");
    }
    atomicAdd(&g_deg[dst], 1.0f);
}

// ---------------------------------------------------------------------------
// K3: epilogue  out = relu(agg / max(deg,1) + b + yr)
// ---------------------------------------------------------------------------
__global__ __launch_bounds__(256) void k_finish(const float* __restrict__ b,
                                                float* __restrict__ out) {
    int i = blockIdx.x * blockDim.x + threadIdx.x;
    if (i >= NN) return;
    float inv = 1.0f / fmaxf(g_deg[i], 1.0f);

    const float4* a4 = reinterpret_cast<const float4*>(g_agg + (size_t)i * NC);
    const float4* y4 = reinterpret_cast<const float4*>(g_yr + (size_t)i * NC);
    const float4* b4 = reinterpret_cast<const float4*>(b);
    float4* o4 = reinterpret_cast<float4*>(out + (size_t)i * NC);
#pragma unroll
    for (int q = 0; q < 4; q++) {
        float4 a = a4[q];
        float4 y = y4[q];
        float4 bb = b4[q];
        float4 o;
        o.x = fmaxf(fmaf(a.x, inv, bb.x + y.x), 0.f);
        o.y = fmaxf(fmaf(a.y, inv, bb.y + y.y), 0.f);
        o.z = fmaxf(fmaf(a.z, inv, bb.z + y.z), 0.f);
        o.w = fmaxf(fmaf(a.w, inv, bb.w + y.w), 0.f);
        o4[q] = o;
    }
}

// ---------------------------------------------------------------------------
// Inputs (metadata order): x [N*F] f32, edge_index [2*E] i32,
//                          W_l [C*F] f32, b_l [C] f32, W_r [C*F] f32
// Output: [N*C] f32
// ---------------------------------------------------------------------------
extern "C" void kernel_launch(void* const* d_in, const int* in_sizes, int n_in,
                              void* d_out, int out_size) {
    const float* x = (const float*)d_in[0];
    const int* ei = (const int*)d_in[1];
    const float* Wl = (const float*)d_in[2];
    const float* bl = (const float*)d_in[3];
    const float* Wr = (const float*)d_in[4];
    float* out = (float*)d_out;

    k_zero<<<(NN * 4 + 255) / 256, 256>>>();
    k_proj<<<(NN + 255) / 256, 256>>>(x, Wl, Wr);
    k_scatter<<<(NE + 255) / 256, 256>>>(ei);
    k_finish<<<(NN + 255) / 256, 256>>>(bl, out);
}